// round 3
// baseline (speedup 1.0000x reference)
#include <cuda_runtime.h>
#include <cuda_bf16.h>

#define UD 128
#define HD 512
#define HC 64
#define NCHUNK 8
#define MT 128
#define THREADS 512
#define DTS 0.1f

// tf32-prerounded weights
__device__ unsigned g_w1[UD * HD];  // [u][h] row-major
__device__ unsigned g_w2[HD * UD];  // [h][u] row-major

__device__ __forceinline__ unsigned tf32r(float x) {
    unsigned r;
    asm("cvt.rna.tf32.f32 %0, %1;" : "=r"(r) : "f"(x));
    return r;
}

__global__ void prep_kernel(const float* __restrict__ W1,
                            const float* __restrict__ W2) {
    int i = blockIdx.x * blockDim.x + threadIdx.x;
    if (i < UD * HD) {
        g_w1[i] = tf32r(W1[i]);
        g_w2[i] = tf32r(W2[i]);
    }
}

// XOR swizzle within a row, 4-float granularity
__device__ __forceinline__ int sw(int r, int c) {
    return ((c & ~3) ^ ((r & 7) << 2)) | (c & 3);
}

__device__ __forceinline__ void mma8(float d[4], const unsigned a[4],
                                     unsigned b0, unsigned b1) {
    asm volatile(
        "mma.sync.aligned.m16n8k8.row.col.f32.tf32.tf32.f32 "
        "{%0,%1,%2,%3}, {%4,%5,%6,%7}, {%8,%9}, {%0,%1,%2,%3};"
        : "+f"(d[0]), "+f"(d[1]), "+f"(d[2]), "+f"(d[3])
        : "r"(a[0]), "r"(a[1]), "r"(a[2]), "r"(a[3]), "r"(b0), "r"(b1));
}

// SMEM (u32 units):
//  sX   @ 0      : 16384  fp32 x, [128][128] swizzled
//  sE   @ 16384  : 16384  tf32 eval point
//  sH   @ 32768  : 8192   tf32 relu chunk [128][64]
//  sW1  @ 40960  : 8192   tf32 W1 chunk [u128][n64]
//  sW2  @ 49152  : 8192   tf32 W2 chunk [k64][n128]
//  sB1  @ 57344  : 512
//  sB2  @ 57856  : 128
#define SMEM_U32 57984

__global__ void __launch_bounds__(THREADS, 1)
rk4_kernel(const float* __restrict__ x0, const float* __restrict__ b1,
           const float* __restrict__ b2, float* __restrict__ xout) {
    extern __shared__ unsigned smem[];
    float*    sX  = (float*)smem;
    unsigned* sE  = smem + 16384;
    unsigned* sH  = smem + 32768;
    unsigned* sW1 = smem + 40960;
    unsigned* sW2 = smem + 49152;
    float*    sB1 = (float*)(smem + 57344);
    float*    sB2 = (float*)(smem + 57856);

    const int tid  = threadIdx.x;
    const int lane = tid & 31;
    const int warp = tid >> 5;
    const int wm   = warp >> 2;   // 0..3  M strip (32 rows)
    const int wn   = warp & 3;    // 0..3  N strip
    const int qr   = lane >> 2;   // 0..7
    const int qc   = lane & 3;    // 0..3

    // ---- load x0 tile -> sX (fp32) and sE (tf32), biases ----
    const float* xg = x0 + (size_t)blockIdx.x * (MT * UD);
    for (int i = tid; i < MT * UD / 4; i += THREADS) {
        int r  = i >> 5;
        int c4 = (i & 31) << 2;
        float4 v = *(const float4*)(xg + r * UD + c4);
        int sc = c4 ^ ((r & 7) << 2);
        *(float4*)(sX + r * UD + sc) = v;
        uint4 e;
        e.x = tf32r(v.x); e.y = tf32r(v.y); e.z = tf32r(v.z); e.w = tf32r(v.w);
        *(uint4*)(sE + r * UD + sc) = e;
    }
    if (tid < HD) sB1[tid] = b1[tid];
    if (tid < UD) sB2[tid] = b2[tid];
    __syncthreads();

    float acc[2][4][4];  // weighted-k accumulator, warp tile M32 x N32
    #pragma unroll
    for (int mi = 0; mi < 2; mi++)
        #pragma unroll
        for (int ni = 0; ni < 4; ni++)
            #pragma unroll
            for (int r = 0; r < 4; r++) acc[mi][ni][r] = 0.0f;

    #pragma unroll 1
    for (int step = 0; step < 20; step++) {
        #pragma unroll 1
        for (int stage = 0; stage < 4; stage++) {
            float out[2][4][4];  // k = f(E) result tile
            #pragma unroll
            for (int mi = 0; mi < 2; mi++)
                #pragma unroll
                for (int ni = 0; ni < 4; ni++)
                    #pragma unroll
                    for (int r = 0; r < 4; r++) out[mi][ni][r] = 0.0f;

            #pragma unroll 1
            for (int ch = 0; ch < NCHUNK; ch++) {
                // ---- load weight chunks (prev chunk compute already synced) ----
                for (int i = tid; i < UD * HC / 4; i += THREADS) {
                    int r  = i >> 4;             // 16 uint4 per 64-col row
                    int c4 = (i & 15) << 2;
                    uint4 v = *(const uint4*)(g_w1 + r * HD + ch * HC + c4);
                    *(uint4*)(sW1 + r * HC + (c4 ^ ((r & 7) << 2))) = v;
                }
                for (int i = tid; i < HC * UD / 4; i += THREADS) {
                    int r  = i >> 5;             // 32 uint4 per 128-col row
                    int c4 = (i & 31) << 2;
                    uint4 v = *(const uint4*)(g_w2 + (ch * HC + r) * UD + c4);
                    *(uint4*)(sW2 + r * UD + (c4 ^ ((r & 7) << 2))) = v;
                }
                __syncthreads();

                // ---- GEMM1: h = E(128x128) @ W1c(128x64), warp: M32 x N16 ----
                float h1[2][2][4];
                #pragma unroll
                for (int mi = 0; mi < 2; mi++)
                    #pragma unroll
                    for (int ni = 0; ni < 2; ni++)
                        #pragma unroll
                        for (int r = 0; r < 4; r++) h1[mi][ni][r] = 0.0f;

                #pragma unroll 4
                for (int k8 = 0; k8 < UD; k8 += 8) {
                    unsigned a[2][4];
                    #pragma unroll
                    for (int mi = 0; mi < 2; mi++) {
                        int r0 = wm * 32 + mi * 16 + qr;
                        a[mi][0] = sE[r0 * UD + sw(r0, k8 + qc)];
                        a[mi][1] = sE[(r0 + 8) * UD + sw(r0 + 8, k8 + qc)];
                        a[mi][2] = sE[r0 * UD + sw(r0, k8 + 4 + qc)];
                        a[mi][3] = sE[(r0 + 8) * UD + sw(r0 + 8, k8 + 4 + qc)];
                    }
                    unsigned bb[2][2];
                    #pragma unroll
                    for (int ni = 0; ni < 2; ni++) {
                        int n0 = wn * 16 + ni * 8 + qr;
                        int kr = k8 + qc;
                        bb[ni][0] = sW1[kr * HC + sw(kr, n0)];
                        bb[ni][1] = sW1[(kr + 4) * HC + sw(kr + 4, n0)];
                    }
                    #pragma unroll
                    for (int mi = 0; mi < 2; mi++)
                        #pragma unroll
                        for (int ni = 0; ni < 2; ni++)
                            mma8(h1[mi][ni], a[mi], bb[ni][0], bb[ni][1]);
                }

                // ---- epilogue1: bias + relu -> sH (tf32) ----
                #pragma unroll
                for (int mi = 0; mi < 2; mi++)
                    #pragma unroll
                    for (int ni = 0; ni < 2; ni++)
                        #pragma unroll
                        for (int r = 0; r < 4; r++) {
                            int row = wm * 32 + mi * 16 + qr + ((r >> 1) << 3);
                            int col = wn * 16 + ni * 8 + 2 * qc + (r & 1);
                            float h = h1[mi][ni][r] + sB1[ch * HC + col];
                            h = fmaxf(h, 0.0f);
                            sH[row * HC + sw(row, col)] = tf32r(h);
                        }
                __syncthreads();

                // ---- GEMM2: out += sH(128x64) @ W2c(64x128), warp: M32 x N32 ----
                #pragma unroll 4
                for (int k8 = 0; k8 < HC; k8 += 8) {
                    unsigned a[2][4];
                    #pragma unroll
                    for (int mi = 0; mi < 2; mi++) {
                        int r0 = wm * 32 + mi * 16 + qr;
                        a[mi][0] = sH[r0 * HC + sw(r0, k8 + qc)];
                        a[mi][1] = sH[(r0 + 8) * HC + sw(r0 + 8, k8 + qc)];
                        a[mi][2] = sH[r0 * HC + sw(r0, k8 + 4 + qc)];
                        a[mi][3] = sH[(r0 + 8) * HC + sw(r0 + 8, k8 + 4 + qc)];
                    }
                    #pragma unroll
                    for (int ni = 0; ni < 4; ni++) {
                        int n0 = wn * 32 + ni * 8 + qr;
                        int kr = k8 + qc;
                        unsigned b0 = sW2[kr * UD + sw(kr, n0)];
                        unsigned b1v = sW2[(kr + 4) * UD + sw(kr + 4, n0)];
                        #pragma unroll
                        for (int mi = 0; mi < 2; mi++)
                            mma8(out[mi][ni], a[mi], b0, b1v);
                    }
                }
                __syncthreads();
            }  // chunks

            // ---- RK4 epilogue for this stage ----
            const float ws = (stage == 0 || stage == 3) ? 1.0f : 2.0f;
            const float cs = (stage == 2) ? DTS : 0.5f * DTS;
            #pragma unroll
            for (int mi = 0; mi < 2; mi++)
                #pragma unroll
                for (int ni = 0; ni < 4; ni++)
                    #pragma unroll
                    for (int r = 0; r < 4; r++) {
                        int row = wm * 32 + mi * 16 + qr + ((r >> 1) << 3);
                        int col = wn * 32 + ni * 8 + 2 * qc + (r & 1);
                        int sc  = sw(row, col);
                        float k = out[mi][ni][r] + sB2[col];
                        float x = sX[row * UD + sc];
                        acc[mi][ni][r] += ws * k;
                        if (stage < 3) {
                            sE[row * UD + sc] = tf32r(x + cs * k);
                        } else {
                            float xn = x + (DTS / 6.0f) * acc[mi][ni][r];
                            sX[row * UD + sc] = xn;
                            sE[row * UD + sc] = tf32r(xn);
                            acc[mi][ni][r] = 0.0f;
                        }
                    }
            __syncthreads();
        }  // stages
    }  // steps

    // ---- write result (de-swizzle) ----
    float* og = xout + (size_t)blockIdx.x * (MT * UD);
    for (int i = tid; i < MT * UD / 4; i += THREADS) {
        int r  = i >> 5;
        int c4 = (i & 31) << 2;
        float4 v = *(const float4*)(sX + r * UD + (c4 ^ ((r & 7) << 2)));
        *(float4*)(og + r * UD + c4) = v;
    }
}

extern "C" void kernel_launch(void* const* d_in, const int* in_sizes, int n_in,
                              void* d_out, int out_size) {
    const float* x0 = (const float*)d_in[0];
    const float* W1 = (const float*)d_in[1];
    const float* b1 = (const float*)d_in[2];
    const float* W2 = (const float*)d_in[3];
    const float* b2 = (const float*)d_in[4];
    float* out = (float*)d_out;

    static bool configured = false;
    if (!configured) {
        cudaFuncSetAttribute(rk4_kernel,
                             cudaFuncAttributeMaxDynamicSharedMemorySize,
                             SMEM_U32 * 4);
        configured = true;
    }

    prep_kernel<<<(UD * HD + 255) / 256, 256>>>(W1, W2);
    rk4_kernel<<<65536 / MT, THREADS, SMEM_U32 * 4>>>(x0, b1, b2, out);
}

// round 5
// speedup vs baseline: 3.0025x; 3.0025x over previous
#include <cuda_runtime.h>
#include <cuda_bf16.h>
#include <cstdint>

#define THREADS 512
#define DTS 0.1f

// bf16 transposed weights: g_w1b [h=512][u=128], g_w2b [u=128][h=512]
__device__ __nv_bfloat16 g_w1b[512 * 128];
__device__ __nv_bfloat16 g_w2b[128 * 512];

__global__ void prep_kernel(const float* __restrict__ W1,
                            const float* __restrict__ W2) {
    int i = blockIdx.x * blockDim.x + threadIdx.x;   // 0..65535
    if (i < 512 * 128) {
        int h = i >> 7, u = i & 127;
        g_w1b[i] = __float2bfloat16_rn(W1[u * 512 + h]);   // [h][u]
        int u2 = i >> 9, h2 = i & 511;
        g_w2b[i] = __float2bfloat16_rn(W2[h2 * 128 + u2]); // [u][h]
    }
}

// ---------------- PTX helpers ----------------
__device__ __forceinline__ uint32_t smem_u32(const void* p) {
    uint32_t a;
    asm("{ .reg .u64 t; cvta.to.shared.u64 t, %1; cvt.u32.u64 %0, t; }"
        : "=r"(a) : "l"(p));
    return a;
}
__device__ __forceinline__ void cp16(uint32_t s, const void* g) {
    asm volatile("cp.async.cg.shared.global [%0], [%1], 16;"
                 :: "r"(s), "l"(g) : "memory");
}
__device__ __forceinline__ void ldm_x4(uint32_t* r, uint32_t addr) {
    asm volatile("ldmatrix.sync.aligned.m8n8.x4.shared.b16 {%0,%1,%2,%3}, [%4];"
                 : "=r"(r[0]), "=r"(r[1]), "=r"(r[2]), "=r"(r[3]) : "r"(addr));
}
__device__ __forceinline__ void ldm_x2(uint32_t* r, uint32_t addr) {
    asm volatile("ldmatrix.sync.aligned.m8n8.x2.shared.b16 {%0,%1}, [%2];"
                 : "=r"(r[0]), "=r"(r[1]) : "r"(addr));
}
__device__ __forceinline__ void mma16(float* d, const uint32_t* a,
                                      const uint32_t* b) {
    asm volatile(
        "mma.sync.aligned.m16n8k16.row.col.f32.bf16.bf16.f32 "
        "{%0,%1,%2,%3},{%4,%5,%6,%7},{%8,%9},{%0,%1,%2,%3};"
        : "+f"(d[0]), "+f"(d[1]), "+f"(d[2]), "+f"(d[3])
        : "r"(a[0]), "r"(a[1]), "r"(a[2]), "r"(a[3]), "r"(b[0]), "r"(b[1]));
}
__device__ __forceinline__ uint32_t packbf(float lo, float hi) {
    uint32_t r;
    asm("cvt.rn.bf16x2.f32 %0, %1, %2;" : "=r"(r) : "f"(hi), "f"(lo));
    return r;
}

// SMEM layout (bytes). Operand tiles are [row][col(bf16)] with 256B rows,
// 16B-granule XOR swizzle: addr(r,c) = r*256 + (((c>>3) ^ (r&7))<<4) + (c&7)*2
#define OFF_E  0            // 32 KB  E (A of GEMM1), 128x128 bf16
#define OFF_H  32768        // 32 KB  H (A of GEMM2)
#define OFF_W1 65536        // 2 x 32 KB double-buffered W1 chunk [n=h128][k=u128]
#define OFF_W2 131072       // 2 x 32 KB double-buffered W2 chunk [n=u128][k=h128]
#define OFF_B1 196608       // 512 fp32
#define OFF_B2 198656       // 128 fp32
#define SMEM_TOTAL 199168

__device__ __forceinline__ void load_w(uint32_t sb, int ch, int buf, int tid) {
    const uint32_t d1b = sb + OFF_W1 + buf * 32768;
    const uint32_t d2b = sb + OFF_W2 + buf * 32768;
    #pragma unroll
    for (int t = 0; t < 4; t++) {
        int i = tid + t * THREADS;        // 0..2047
        int n = i >> 4, g = i & 15;
        // W1 chunk: rows n = chunk-local h, k = u (128)
        cp16(d1b + n * 256 + ((g ^ (n & 7)) << 4),
             g_w1b + (ch * 128 + n) * 128 + g * 8);
        // W2 chunk: rows n = u, k = chunk-local h (128)
        cp16(d2b + n * 256 + ((g ^ (n & 7)) << 4),
             g_w2b + n * 512 + ch * 128 + g * 8);
    }
    asm volatile("cp.async.commit_group;" ::: "memory");
}

__global__ void __launch_bounds__(THREADS, 1)
rk4_kernel(const float* __restrict__ x0, const float* __restrict__ b1g,
           const float* __restrict__ b2g, float* __restrict__ xout) {
    extern __shared__ unsigned char smem[];
    const uint32_t sb = smem_u32(smem);
    float* sB1 = (float*)(smem + OFF_B1);
    float* sB2 = (float*)(smem + OFF_B2);

    const int tid  = threadIdx.x;
    const int lane = tid & 31;
    const int wid  = tid >> 5;
    const int qr   = lane >> 2;
    const int qc   = lane & 3;
    const int wm   = wid >> 2;     // M strip (32 rows)
    const int wn   = wid & 3;      // N strip (32 cols)

    if (tid < 512) sB1[tid] = b1g[tid];
    if (tid < 128) sB2[tid] = b2g[tid];

    // ---- init: x0 -> xout (fp32 state) and sE (bf16, swizzled) ----
    const float* xg = x0   + (size_t)blockIdx.x * 16384;
    float*       xo = xout + (size_t)blockIdx.x * 16384;
    for (int i = tid; i < 8192; i += THREADS) {   // one bf16x2 word each
        int r = i >> 6, c = (i & 63) << 1;
        float2 v = *(const float2*)(xg + r * 128 + c);
        *(float2*)(xo + r * 128 + c) = v;
        uint32_t w = packbf(v.x, v.y);
        *(uint32_t*)(smem + OFF_E + r * 256 + (((c >> 3) ^ (r & 7)) << 4) +
                     (c & 7) * 2) = w;
    }

    load_w(sb, 0, 0, tid);
    __syncthreads();

    // per-lane ldmatrix address components
    const int arow = wm * 32 + ((lane >> 3) & 1) * 8 + (lane & 7); // + mi*16
    const int asel = lane >> 4;            // col-granule half for A
    const int alow = lane & 7;
    const int brow = (lane & 7);           // B row within 8-group
    const int bsel = (lane >> 3) & 1;      // B col-granule half

    float acc[32];
    #pragma unroll
    for (int i = 0; i < 32; i++) acc[i] = 0.0f;

    #pragma unroll 1
    for (int ev = 0; ev < 80; ev++) {
        const int stage = ev & 3;
        const float ws = (stage == 0 || stage == 3) ? 1.0f : 2.0f;
        const float cs = (stage == 2) ? DTS : 0.5f * DTS;

        float out[32];
        #pragma unroll
        for (int i = 0; i < 32; i++) out[i] = 0.0f;

        #pragma unroll 1
        for (int ch = 0; ch < 4; ch++) {
            const int buf = ch & 1;
            asm volatile("cp.async.wait_group 0;" ::: "memory");
            __syncthreads();
            load_w(sb, (ch + 1) & 3, buf ^ 1, tid);

            const uint32_t w1b = sb + OFF_W1 + buf * 32768;
            const uint32_t w2b = sb + OFF_W2 + buf * 32768;

            // ---- GEMM1: h1 = E(128x128) @ W1c^T, warp tile M32 x N32 ----
            float h1[32];
            #pragma unroll
            for (int i = 0; i < 32; i++) h1[i] = 0.0f;
            #pragma unroll
            for (int k16 = 0; k16 < 8; k16++) {
                uint32_t a[2][4], bf[4][2];
                #pragma unroll
                for (int mi = 0; mi < 2; mi++)
                    ldm_x4(a[mi], sb + OFF_E + (arow + mi * 16) * 256 +
                                  (((2 * k16 + asel) ^ alow) << 4));
                #pragma unroll
                for (int ni = 0; ni < 4; ni++) {
                    int n = wn * 32 + ni * 8 + brow;
                    ldm_x2(bf[ni], w1b + n * 256 +
                                   (((2 * k16 + bsel) ^ (n & 7)) << 4));
                }
                #pragma unroll
                for (int mi = 0; mi < 2; mi++)
                    #pragma unroll
                    for (int ni = 0; ni < 4; ni++)
                        mma16(h1 + (mi * 4 + ni) * 4, a[mi], bf[ni]);
            }

            // ---- epilogue1: bias + relu -> sH (bf16x2 stores) ----
            #pragma unroll
            for (int mi = 0; mi < 2; mi++)
                #pragma unroll
                for (int ni = 0; ni < 4; ni++) {
                    const int q   = (mi * 4 + ni) * 4;
                    const int row = wm * 32 + mi * 16 + qr;
                    const int col = wn * 32 + ni * 8 + 2 * qc;
                    float bb0 = sB1[ch * 128 + col], bb1 = sB1[ch * 128 + col + 1];
                    uint32_t w0 = packbf(fmaxf(h1[q + 0] + bb0, 0.0f),
                                         fmaxf(h1[q + 1] + bb1, 0.0f));
                    uint32_t w1 = packbf(fmaxf(h1[q + 2] + bb0, 0.0f),
                                         fmaxf(h1[q + 3] + bb1, 0.0f));
                    uint32_t base = (((col >> 3) ^ (row & 7)) << 4) + (col & 7) * 2;
                    *(uint32_t*)(smem + OFF_H + row * 256 + base) = w0;
                    *(uint32_t*)(smem + OFF_H + (row + 8) * 256 +
                                 ((((col >> 3) ^ ((row + 8) & 7)) << 4) +
                                  (col & 7) * 2)) = w1;
                }
            __syncthreads();

            // ---- GEMM2: out += H(128x128) @ W2c^T ----
            #pragma unroll
            for (int k16 = 0; k16 < 8; k16++) {
                uint32_t a[2][4], bf[4][2];
                #pragma unroll
                for (int mi = 0; mi < 2; mi++)
                    ldm_x4(a[mi], sb + OFF_H + (arow + mi * 16) * 256 +
                                  (((2 * k16 + asel) ^ alow) << 4));
                #pragma unroll
                for (int ni = 0; ni < 4; ni++) {
                    int n = wn * 32 + ni * 8 + brow;
                    ldm_x2(bf[ni], w2b + n * 256 +
                                   (((2 * k16 + bsel) ^ (n & 7)) << 4));
                }
                #pragma unroll
                for (int mi = 0; mi < 2; mi++)
                    #pragma unroll
                    for (int ni = 0; ni < 4; ni++)
                        mma16(out + (mi * 4 + ni) * 4, a[mi], bf[ni]);
            }
        }  // chunks

        // ---- RK4 stage epilogue (x lives in xout, thread-private mapping) ----
        #pragma unroll
        for (int mi = 0; mi < 2; mi++)
            #pragma unroll
            for (int ni = 0; ni < 4; ni++) {
                const int q   = (mi * 4 + ni) * 4;
                const int row = wm * 32 + mi * 16 + qr;
                const int col = wn * 32 + ni * 8 + 2 * qc;
                float2* xp0 = (float2*)(xo + row * 128 + col);
                float2* xp1 = (float2*)(xo + (row + 8) * 128 + col);
                float2 xv0 = *xp0, xv1 = *xp1;
                float k0 = out[q + 0] + sB2[col];
                float k1 = out[q + 1] + sB2[col + 1];
                float k2 = out[q + 2] + sB2[col];
                float k3 = out[q + 3] + sB2[col + 1];
                acc[q + 0] += ws * k0; acc[q + 1] += ws * k1;
                acc[q + 2] += ws * k2; acc[q + 3] += ws * k3;
                uint32_t w0, w1;
                if (stage < 3) {
                    w0 = packbf(xv0.x + cs * k0, xv0.y + cs * k1);
                    w1 = packbf(xv1.x + cs * k2, xv1.y + cs * k3);
                } else {
                    float n0 = xv0.x + (DTS / 6.0f) * acc[q + 0];
                    float n1 = xv0.y + (DTS / 6.0f) * acc[q + 1];
                    float n2 = xv1.x + (DTS / 6.0f) * acc[q + 2];
                    float n3 = xv1.y + (DTS / 6.0f) * acc[q + 3];
                    *xp0 = make_float2(n0, n1);
                    *xp1 = make_float2(n2, n3);
                    acc[q + 0] = acc[q + 1] = acc[q + 2] = acc[q + 3] = 0.0f;
                    w0 = packbf(n0, n1);
                    w1 = packbf(n2, n3);
                }
                *(uint32_t*)(smem + OFF_E + row * 256 +
                             ((((col >> 3) ^ (row & 7)) << 4) + (col & 7) * 2)) = w0;
                *(uint32_t*)(smem + OFF_E + (row + 8) * 256 +
                             ((((col >> 3) ^ ((row + 8) & 7)) << 4) +
                              (col & 7) * 2)) = w1;
            }
        // next eval's first chunk syncs before reading sE
    }  // evals

    asm volatile("cp.async.wait_group 0;" ::: "memory");
}

extern "C" void kernel_launch(void* const* d_in, const int* in_sizes, int n_in,
                              void* d_out, int out_size) {
    const float* x0 = (const float*)d_in[0];
    const float* W1 = (const float*)d_in[1];
    const float* b1 = (const float*)d_in[2];
    const float* W2 = (const float*)d_in[3];
    const float* b2 = (const float*)d_in[4];
    float* out = (float*)d_out;

    static bool configured = false;
    if (!configured) {
        cudaFuncSetAttribute(rk4_kernel,
                             cudaFuncAttributeMaxDynamicSharedMemorySize,
                             SMEM_TOTAL);
        configured = true;
    }

    prep_kernel<<<256, 256>>>(W1, W2);
    rk4_kernel<<<512, THREADS, SMEM_TOTAL>>>(x0, b1, b2, out);
}

// round 6
// speedup vs baseline: 3.7181x; 1.2384x over previous
#include <cuda_runtime.h>
#include <cuda_bf16.h>
#include <cstdint>

#define THREADS 256
#define MROWS 64
#define DTS 0.1f

// bf16 transposed weights: g_w1b [h=512][u=128], g_w2b [u=128][h=512]
__device__ __nv_bfloat16 g_w1b[512 * 128];
__device__ __nv_bfloat16 g_w2b[128 * 512];

__global__ void prep_kernel(const float* __restrict__ W1,
                            const float* __restrict__ W2) {
    int i = blockIdx.x * blockDim.x + threadIdx.x;   // 0..65535
    if (i < 512 * 128) {
        int h = i >> 7, u = i & 127;
        g_w1b[i] = __float2bfloat16_rn(W1[u * 512 + h]);   // [h][u]
        int u2 = i >> 9, h2 = i & 511;
        g_w2b[i] = __float2bfloat16_rn(W2[h2 * 128 + u2]); // [u][h]
    }
}

// ---------------- PTX helpers ----------------
__device__ __forceinline__ uint32_t smem_u32(const void* p) {
    uint32_t a;
    asm("{ .reg .u64 t; cvta.to.shared.u64 t, %1; cvt.u32.u64 %0, t; }"
        : "=r"(a) : "l"(p));
    return a;
}
__device__ __forceinline__ void cp16(uint32_t s, const void* g) {
    asm volatile("cp.async.cg.shared.global [%0], [%1], 16;"
                 :: "r"(s), "l"(g) : "memory");
}
__device__ __forceinline__ void ldm_x4(uint32_t* r, uint32_t addr) {
    asm volatile("ldmatrix.sync.aligned.m8n8.x4.shared.b16 {%0,%1,%2,%3}, [%4];"
                 : "=r"(r[0]), "=r"(r[1]), "=r"(r[2]), "=r"(r[3]) : "r"(addr));
}
__device__ __forceinline__ void mma16(float* d, const uint32_t* a,
                                      const uint32_t* b) {
    asm volatile(
        "mma.sync.aligned.m16n8k16.row.col.f32.bf16.bf16.f32 "
        "{%0,%1,%2,%3},{%4,%5,%6,%7},{%8,%9},{%0,%1,%2,%3};"
        : "+f"(d[0]), "+f"(d[1]), "+f"(d[2]), "+f"(d[3])
        : "r"(a[0]), "r"(a[1]), "r"(a[2]), "r"(a[3]), "r"(b[0]), "r"(b[1]));
}
__device__ __forceinline__ uint32_t packbf(float lo, float hi) {
    uint32_t r;
    asm("cvt.rn.bf16x2.f32 %0, %1, %2;" : "=r"(r) : "f"(hi), "f"(lo));
    return r;
}

// SMEM layout (bytes). Tiles are [row][col bf16], 256B rows,
// 16B-granule XOR swizzle: addr(r,c) = r*256 + (((c>>3) ^ (r&7))<<4) + (c&7)*2
#define OFF_E  0            // 16 KB  E (A of GEMM1), 64x128 bf16
#define OFF_H  16384        // 16 KB  H (A of GEMM2), 64x128 bf16
#define OFF_W1 32768        // 32 KB  W1 chunk [n=h128][k=u128]   (single buffer)
#define OFF_W2 65536        // 32 KB  W2 chunk [n=u128][k=h128]   (single buffer)
#define OFF_B1 98304        // 512 fp32
#define OFF_B2 100352       // 128 fp32
#define SMEM_TOTAL 100864

__device__ __forceinline__ void load_w1(uint32_t sb, int ch, int tid) {
    const uint32_t d = sb + OFF_W1;
    #pragma unroll
    for (int t = 0; t < 8; t++) {
        int i = tid + t * THREADS;        // 0..2047
        int n = i >> 4, g = i & 15;
        cp16(d + n * 256 + ((g ^ (n & 7)) << 4),
             g_w1b + (ch * 128 + n) * 128 + g * 8);
    }
    asm volatile("cp.async.commit_group;" ::: "memory");
}
__device__ __forceinline__ void load_w2(uint32_t sb, int ch, int tid) {
    const uint32_t d = sb + OFF_W2;
    #pragma unroll
    for (int t = 0; t < 8; t++) {
        int i = tid + t * THREADS;
        int n = i >> 4, g = i & 15;
        cp16(d + n * 256 + ((g ^ (n & 7)) << 4),
             g_w2b + n * 512 + ch * 128 + g * 8);
    }
    asm volatile("cp.async.commit_group;" ::: "memory");
}

__global__ void __launch_bounds__(THREADS, 2)
rk4_kernel(const float* __restrict__ x0, const float* __restrict__ b1g,
           const float* __restrict__ b2g, float* __restrict__ xout) {
    extern __shared__ unsigned char smem[];
    const uint32_t sb = smem_u32(smem);
    float* sB1 = (float*)(smem + OFF_B1);
    float* sB2 = (float*)(smem + OFF_B2);

    const int tid  = threadIdx.x;
    const int lane = tid & 31;
    const int wid  = tid >> 5;     // 0..7
    const int qr   = lane >> 2;
    const int qc   = lane & 3;
    const int wm   = wid >> 2;     // 0..1  M strip (32 rows)
    const int wn   = wid & 3;      // 0..3  N strip (32 cols)

    sB1[tid] = b1g[tid];
    sB1[tid + 256] = b1g[tid + 256];
    if (tid < 128) sB2[tid] = b2g[tid];

    // ---- init: x0 -> xout (fp32 state) and sE (bf16, swizzled) ----
    const float* xg = x0   + (size_t)blockIdx.x * (MROWS * 128);
    float*       xo = xout + (size_t)blockIdx.x * (MROWS * 128);
    for (int i = tid; i < MROWS * 64; i += THREADS) {   // one bf16x2 each
        int r = i >> 6, c = (i & 63) << 1;
        float2 v = *(const float2*)(xg + r * 128 + c);
        *(float2*)(xo + r * 128 + c) = v;
        *(uint32_t*)(smem + OFF_E + r * 256 + (((c >> 3) ^ (r & 7)) << 4) +
                     (c & 7) * 2) = packbf(v.x, v.y);
    }

    load_w1(sb, 0, tid);
    asm volatile("cp.async.wait_group 0;" ::: "memory");
    __syncthreads();

    // ldmatrix lane address components
    const int arow0 = wm * 32 + ((lane >> 3) & 1) * 8 + (lane & 7);  // +mi*16
    const int asel  = lane >> 4;            // k8-half for A
    const int brow0 = ((lane >> 4) << 3) + (lane & 7);               // +pair*16
    const int bsel  = (lane >> 3) & 1;      // k8-half for B

    float acc[32];
    #pragma unroll
    for (int i = 0; i < 32; i++) acc[i] = 0.0f;

    #pragma unroll 1
    for (int ev = 0; ev < 80; ev++) {
        const int stage = ev & 3;
        const float ws = (stage == 0 || stage == 3) ? 1.0f : 2.0f;
        const float cs = (stage == 2) ? DTS : 0.5f * DTS;

        float out[32];
        #pragma unroll
        for (int i = 0; i < 32; i++) out[i] = 0.0f;

        #pragma unroll 1
        for (int ch = 0; ch < 4; ch++) {
            // W2 buffer is free (G2 of prev chunk done before last barrier)
            load_w2(sb, ch, tid);

            // ---- GEMM1: h1 = E(64x128) @ W1c^T, warp tile M32 x N32 ----
            float h1[32];
            #pragma unroll
            for (int i = 0; i < 32; i++) h1[i] = 0.0f;
            #pragma unroll
            for (int k16 = 0; k16 < 8; k16++) {
                uint32_t a[2][4], b[2][4];
                #pragma unroll
                for (int mi = 0; mi < 2; mi++) {
                    int r = arow0 + mi * 16;
                    ldm_x4(a[mi], sb + OFF_E + r * 256 +
                                  (((2 * k16 + asel) ^ (r & 7)) << 4));
                }
                #pragma unroll
                for (int pr = 0; pr < 2; pr++) {
                    int n = wn * 32 + pr * 16 + brow0;
                    ldm_x4(b[pr], sb + OFF_W1 + n * 256 +
                                  (((2 * k16 + bsel) ^ (n & 7)) << 4));
                }
                #pragma unroll
                for (int mi = 0; mi < 2; mi++)
                    #pragma unroll
                    for (int pr = 0; pr < 2; pr++)
                        #pragma unroll
                        for (int j = 0; j < 2; j++)
                            mma16(h1 + (mi * 4 + pr * 2 + j) * 4,
                                  a[mi], &b[pr][2 * j]);
            }

            // ---- epilogue1: bias + relu -> sH (bf16x2 stores) ----
            #pragma unroll
            for (int mi = 0; mi < 2; mi++)
                #pragma unroll
                for (int ni = 0; ni < 4; ni++) {
                    const int q   = (mi * 4 + ni) * 4;
                    const int row = wm * 32 + mi * 16 + qr;
                    const int col = wn * 32 + ni * 8 + 2 * qc;
                    float bb0 = sB1[ch * 128 + col], bb1 = sB1[ch * 128 + col + 1];
                    uint32_t w0 = packbf(fmaxf(h1[q + 0] + bb0, 0.0f),
                                         fmaxf(h1[q + 1] + bb1, 0.0f));
                    uint32_t w1 = packbf(fmaxf(h1[q + 2] + bb0, 0.0f),
                                         fmaxf(h1[q + 3] + bb1, 0.0f));
                    *(uint32_t*)(smem + OFF_H + row * 256 +
                                 ((((col >> 3) ^ (row & 7)) << 4) +
                                  (col & 7) * 2)) = w0;
                    *(uint32_t*)(smem + OFF_H + (row + 8) * 256 +
                                 ((((col >> 3) ^ ((row + 8) & 7)) << 4) +
                                  (col & 7) * 2)) = w1;
                }
            asm volatile("cp.async.wait_group 0;" ::: "memory");
            __syncthreads();   // H + W2(ch) visible; W1 buffer now free

            load_w1(sb, (ch + 1) & 3, tid);  // for next chunk / next eval

            // ---- GEMM2: out += H(64x128) @ W2c^T, warp tile M32 x N32 ----
            #pragma unroll
            for (int k16 = 0; k16 < 8; k16++) {
                uint32_t a[2][4], b[2][4];
                #pragma unroll
                for (int mi = 0; mi < 2; mi++) {
                    int r = arow0 + mi * 16;
                    ldm_x4(a[mi], sb + OFF_H + r * 256 +
                                  (((2 * k16 + asel) ^ (r & 7)) << 4));
                }
                #pragma unroll
                for (int pr = 0; pr < 2; pr++) {
                    int n = wn * 32 + pr * 16 + brow0;
                    ldm_x4(b[pr], sb + OFF_W2 + n * 256 +
                                  (((2 * k16 + bsel) ^ (n & 7)) << 4));
                }
                #pragma unroll
                for (int mi = 0; mi < 2; mi++)
                    #pragma unroll
                    for (int pr = 0; pr < 2; pr++)
                        #pragma unroll
                        for (int j = 0; j < 2; j++)
                            mma16(out + (mi * 4 + pr * 2 + j) * 4,
                                  a[mi], &b[pr][2 * j]);
            }
            asm volatile("cp.async.wait_group 0;" ::: "memory");
            __syncthreads();   // W1(next) visible; H/W2 buffers free
        }  // chunks

        // ---- RK4 stage epilogue (x lives in xout) ----
        #pragma unroll
        for (int mi = 0; mi < 2; mi++)
            #pragma unroll
            for (int ni = 0; ni < 4; ni++) {
                const int q   = (mi * 4 + ni) * 4;
                const int row = wm * 32 + mi * 16 + qr;
                const int col = wn * 32 + ni * 8 + 2 * qc;
                float2* xp0 = (float2*)(xo + row * 128 + col);
                float2* xp1 = (float2*)(xo + (row + 8) * 128 + col);
                float2 xv0 = *xp0, xv1 = *xp1;
                float k0 = out[q + 0] + sB2[col];
                float k1 = out[q + 1] + sB2[col + 1];
                float k2 = out[q + 2] + sB2[col];
                float k3 = out[q + 3] + sB2[col + 1];
                acc[q + 0] += ws * k0; acc[q + 1] += ws * k1;
                acc[q + 2] += ws * k2; acc[q + 3] += ws * k3;
                uint32_t w0, w1;
                if (stage < 3) {
                    w0 = packbf(xv0.x + cs * k0, xv0.y + cs * k1);
                    w1 = packbf(xv1.x + cs * k2, xv1.y + cs * k3);
                } else {
                    float n0 = xv0.x + (DTS / 6.0f) * acc[q + 0];
                    float n1 = xv0.y + (DTS / 6.0f) * acc[q + 1];
                    float n2 = xv1.x + (DTS / 6.0f) * acc[q + 2];
                    float n3 = xv1.y + (DTS / 6.0f) * acc[q + 3];
                    *xp0 = make_float2(n0, n1);
                    *xp1 = make_float2(n2, n3);
                    acc[q + 0] = acc[q + 1] = acc[q + 2] = acc[q + 3] = 0.0f;
                    w0 = packbf(n0, n1);
                    w1 = packbf(n2, n3);
                }
                *(uint32_t*)(smem + OFF_E + row * 256 +
                             ((((col >> 3) ^ (row & 7)) << 4) + (col & 7) * 2)) = w0;
                *(uint32_t*)(smem + OFF_E + (row + 8) * 256 +
                             ((((col >> 3) ^ ((row + 8) & 7)) << 4) +
                              (col & 7) * 2)) = w1;
            }
        __syncthreads();   // E visible before next eval's GEMM1
    }  // evals
}

extern "C" void kernel_launch(void* const* d_in, const int* in_sizes, int n_in,
                              void* d_out, int out_size) {
    const float* x0 = (const float*)d_in[0];
    const float* W1 = (const float*)d_in[1];
    const float* b1 = (const float*)d_in[2];
    const float* W2 = (const float*)d_in[3];
    const float* b2 = (const float*)d_in[4];
    float* out = (float*)d_out;

    static bool configured = false;
    if (!configured) {
        cudaFuncSetAttribute(rk4_kernel,
                             cudaFuncAttributeMaxDynamicSharedMemorySize,
                             SMEM_TOTAL);
        configured = true;
    }

    prep_kernel<<<256, 256>>>(W1, W2);
    rk4_kernel<<<65536 / MROWS, THREADS, SMEM_TOTAL>>>(x0, b1, b2, out);
}

// round 7
// speedup vs baseline: 4.1569x; 1.1180x over previous
#include <cuda_runtime.h>
#include <cuda_bf16.h>
#include <cstdint>

#define THREADS 256
#define MROWS 64
#define DTS 0.1f

// Pre-swizzled, chunk-blocked bf16 weights. Each 32 KB chunk block is a
// byte-exact image of the SMEM weight buffer, so a single linear bulk copy
// reproduces what R5's 2048 cp.async built.
// Layout per chunk block: granule(n,g) at byte  n*256 + ((g^(n&7))<<4),
// holding 8 bf16.
__device__ __nv_bfloat16 g_w1s[4 * 16384];  // W1^T chunks: [ch][n=h128][u=g*8+j]
__device__ __nv_bfloat16 g_w2s[4 * 16384];  // W2^T chunks: [ch][n=u128][h=g*8+j]

__global__ void prep_kernel(const float* __restrict__ W1,
                            const float* __restrict__ W2) {
    int i = blockIdx.x * blockDim.x + threadIdx.x;   // granule id, 0..16383
    if (i >= 16384) return;
    int arr = i >> 13;          // 0 = W1, 1 = W2
    int idx = i & 8191;
    int ch = idx >> 11;
    int n  = (idx >> 4) & 127;
    int g  = idx & 15;
    uint32_t off = (uint32_t)ch * 32768 + n * 256 + ((g ^ (n & 7)) << 4);
    __nv_bfloat16 v[8];
    if (arr == 0) {
        // W1t[h = ch*128+n][u = g*8+j] = W1[u*512 + h]
        #pragma unroll
        for (int j = 0; j < 8; j++)
            v[j] = __float2bfloat16_rn(W1[(g * 8 + j) * 512 + ch * 128 + n]);
        *(uint4*)((char*)g_w1s + off) = *(uint4*)v;
    } else {
        // W2t[u = n][h = ch*128 + g*8+j] = W2[h*128 + u]
        #pragma unroll
        for (int j = 0; j < 8; j++)
            v[j] = __float2bfloat16_rn(W2[(ch * 128 + g * 8 + j) * 128 + n]);
        *(uint4*)((char*)g_w2s + off) = *(uint4*)v;
    }
}

// ---------------- PTX helpers ----------------
__device__ __forceinline__ uint32_t smem_u32(const void* p) {
    uint32_t a;
    asm("{ .reg .u64 t; cvta.to.shared.u64 t, %1; cvt.u32.u64 %0, t; }"
        : "=r"(a) : "l"(p));
    return a;
}
__device__ __forceinline__ void ldm_x4(uint32_t* r, uint32_t addr) {
    asm volatile("ldmatrix.sync.aligned.m8n8.x4.shared.b16 {%0,%1,%2,%3}, [%4];"
                 : "=r"(r[0]), "=r"(r[1]), "=r"(r[2]), "=r"(r[3]) : "r"(addr));
}
__device__ __forceinline__ void mma16(float* d, const uint32_t* a,
                                      const uint32_t* b) {
    asm volatile(
        "mma.sync.aligned.m16n8k16.row.col.f32.bf16.bf16.f32 "
        "{%0,%1,%2,%3},{%4,%5,%6,%7},{%8,%9},{%0,%1,%2,%3};"
        : "+f"(d[0]), "+f"(d[1]), "+f"(d[2]), "+f"(d[3])
        : "r"(a[0]), "r"(a[1]), "r"(a[2]), "r"(a[3]), "r"(b[0]), "r"(b[1]));
}
__device__ __forceinline__ uint32_t packbf(float lo, float hi) {
    uint32_t r;
    asm("cvt.rn.bf16x2.f32 %0, %1, %2;" : "=r"(r) : "f"(hi), "f"(lo));
    return r;
}
__device__ __forceinline__ void bulk_g2s(uint32_t dst, const void* src,
                                         uint32_t bytes, uint32_t mb) {
    asm volatile(
        "cp.async.bulk.shared::cta.global.mbarrier::complete_tx::bytes "
        "[%0], [%1], %2, [%3];"
        :: "r"(dst), "l"(src), "r"(bytes), "r"(mb) : "memory");
}
#define MBARRIER_INIT(mb, c) \
    asm volatile("mbarrier.init.shared.b64 [%0], %1;" \
                 :: "r"((uint32_t)(mb)), "r"((uint32_t)(c)) : "memory")
#define MBARRIER_EXPECT_TX(mb, n) \
    asm volatile("mbarrier.arrive.expect_tx.shared.b64 _, [%0], %1;" \
                 :: "r"((uint32_t)(mb)), "r"((uint32_t)(n)) : "memory")
#define MBARRIER_WAIT_PARITY(mb, par) do {                                   \
    uint32_t _mb = (uint32_t)(mb), _pa = (uint32_t)(par), _done;             \
    asm volatile("{ .reg .pred p; mbarrier.try_wait.parity.acquire.cta.shared::cta.b64 p, [%1], %2; selp.b32 %0,1,0,p; }" \
                 : "=r"(_done) : "r"(_mb), "r"(_pa) : "memory");             \
    if (!_done) {                                                            \
        asm volatile("{ .reg .pred P1; WL_%=: mbarrier.try_wait.parity.acquire.cta.shared::cta.b64 P1, [%0], %1, 0x989680; @P1 bra.uni WD_%=; bra.uni WL_%=; WD_%=: }" \
                     :: "r"(_mb), "r"(_pa) : "memory");                      \
    } } while (0)

// SMEM layout (bytes). Activation tiles [row][col bf16], 256B rows,
// 16B-granule XOR swizzle: addr(r,c) = r*256 + (((c>>3) ^ (r&7))<<4) + (c&7)*2
#define OFF_E   0            // 16 KB  E (A of GEMM1), 64x128 bf16
#define OFF_H   16384        // 16 KB  H (A of GEMM2), 64x128 bf16
#define OFF_W1  32768        // 32 KB  W1 chunk [n=h128][k=u128]
#define OFF_W2  65536        // 32 KB  W2 chunk [n=u128][k=h128]
#define OFF_B1  98304        // 512 fp32
#define OFF_B2  100352       // 128 fp32
#define OFF_MB1 100864       // 8 B mbarrier (W1)
#define OFF_MB2 100872       // 8 B mbarrier (W2)
#define SMEM_TOTAL 100992

__global__ void __launch_bounds__(THREADS, 2)
rk4_kernel(const float* __restrict__ x0, const float* __restrict__ b1g,
           const float* __restrict__ b2g, float* __restrict__ xout) {
    extern __shared__ unsigned char smem[];
    const uint32_t sb = smem_u32(smem);
    float* sB1 = (float*)(smem + OFF_B1);
    float* sB2 = (float*)(smem + OFF_B2);

    const int tid  = threadIdx.x;
    const int lane = tid & 31;
    const int wid  = tid >> 5;     // 0..7
    const int qr   = lane >> 2;
    const int qc   = lane & 3;
    const int wm   = wid >> 2;     // 0..1  M strip (32 rows)
    const int wn   = wid & 3;      // 0..3  N strip (32 cols)

    if (tid == 0) { MBARRIER_INIT(sb + OFF_MB1, 1); MBARRIER_INIT(sb + OFF_MB2, 1); }
    sB1[tid] = b1g[tid];
    sB1[tid + 256] = b1g[tid + 256];
    if (tid < 128) sB2[tid] = b2g[tid];

    // ---- init: x0 -> xout (fp32 state) and sE (bf16, swizzled) ----
    const float* xg = x0   + (size_t)blockIdx.x * (MROWS * 128);
    float*       xo = xout + (size_t)blockIdx.x * (MROWS * 128);
    for (int i = tid; i < MROWS * 64; i += THREADS) {   // one bf16x2 each
        int r = i >> 6, c = (i & 63) << 1;
        float2 v = *(const float2*)(xg + r * 128 + c);
        *(float2*)(xo + r * 128 + c) = v;
        *(uint32_t*)(smem + OFF_E + r * 256 + (((c >> 3) ^ (r & 7)) << 4) +
                     (c & 7) * 2) = packbf(v.x, v.y);
    }
    __syncthreads();   // mbarriers initialized, sE/biases written

    if (tid == 0) {
        MBARRIER_EXPECT_TX(sb + OFF_MB1, 32768);
        bulk_g2s(sb + OFF_W1, g_w1s, 32768, sb + OFF_MB1);
    }

    // ldmatrix lane address components
    const int arow0 = wm * 32 + ((lane >> 3) & 1) * 8 + (lane & 7);  // +mi*16
    const int asel  = lane >> 4;            // k8-half for A
    const int brow0 = ((lane >> 4) << 3) + (lane & 7);               // +pair*16
    const int bsel  = (lane >> 3) & 1;      // k8-half for B

    float acc[32];
    #pragma unroll
    for (int i = 0; i < 32; i++) acc[i] = 0.0f;

    int p1 = 0, p2 = 0;   // mbarrier phase parities

    #pragma unroll 1
    for (int ev = 0; ev < 80; ev++) {
        const int stage = ev & 3;
        const float ws = (stage == 0 || stage == 3) ? 1.0f : 2.0f;
        const float cs = (stage == 2) ? DTS : 0.5f * DTS;

        float out[32];
        #pragma unroll
        for (int i = 0; i < 32; i++) out[i] = 0.0f;

        #pragma unroll 1
        for (int ch = 0; ch < 4; ch++) {
            // W2 buffer free (G2 of prev chunk done before last barrier)
            if (tid == 0) {
                MBARRIER_EXPECT_TX(sb + OFF_MB2, 32768);
                bulk_g2s(sb + OFF_W2, (const char*)g_w2s + ch * 32768,
                         32768, sb + OFF_MB2);
            }

            // wait W1(ch)
            MBARRIER_WAIT_PARITY(sb + OFF_MB1, p1); p1 ^= 1;

            // ---- GEMM1: h1 = E(64x128) @ W1c^T, warp tile M32 x N32 ----
            float h1[32];
            #pragma unroll
            for (int i = 0; i < 32; i++) h1[i] = 0.0f;
            #pragma unroll
            for (int k16 = 0; k16 < 8; k16++) {
                uint32_t a[2][4], b[2][4];
                #pragma unroll
                for (int mi = 0; mi < 2; mi++) {
                    int r = arow0 + mi * 16;
                    ldm_x4(a[mi], sb + OFF_E + r * 256 +
                                  (((2 * k16 + asel) ^ (r & 7)) << 4));
                }
                #pragma unroll
                for (int pr = 0; pr < 2; pr++) {
                    int n = wn * 32 + pr * 16 + brow0;
                    ldm_x4(b[pr], sb + OFF_W1 + n * 256 +
                                  (((2 * k16 + bsel) ^ (n & 7)) << 4));
                }
                #pragma unroll
                for (int mi = 0; mi < 2; mi++)
                    #pragma unroll
                    for (int pr = 0; pr < 2; pr++)
                        #pragma unroll
                        for (int j = 0; j < 2; j++)
                            mma16(h1 + (mi * 4 + pr * 2 + j) * 4,
                                  a[mi], &b[pr][2 * j]);
            }

            // ---- epilogue1: bias + relu -> sH (bf16x2 stores) ----
            #pragma unroll
            for (int mi = 0; mi < 2; mi++)
                #pragma unroll
                for (int ni = 0; ni < 4; ni++) {
                    const int q   = (mi * 4 + ni) * 4;
                    const int row = wm * 32 + mi * 16 + qr;
                    const int col = wn * 32 + ni * 8 + 2 * qc;
                    float bb0 = sB1[ch * 128 + col], bb1 = sB1[ch * 128 + col + 1];
                    uint32_t w0 = packbf(fmaxf(h1[q + 0] + bb0, 0.0f),
                                         fmaxf(h1[q + 1] + bb1, 0.0f));
                    uint32_t w1 = packbf(fmaxf(h1[q + 2] + bb0, 0.0f),
                                         fmaxf(h1[q + 3] + bb1, 0.0f));
                    *(uint32_t*)(smem + OFF_H + row * 256 +
                                 ((((col >> 3) ^ (row & 7)) << 4) +
                                  (col & 7) * 2)) = w0;
                    *(uint32_t*)(smem + OFF_H + (row + 8) * 256 +
                                 ((((col >> 3) ^ ((row + 8) & 7)) << 4) +
                                  (col & 7) * 2)) = w1;
                }
            __syncthreads();   // H visible; all warps done reading W1

            // prefetch W1 for next chunk (skip on the very last chunk)
            if (tid == 0 && !(ev == 79 && ch == 3)) {
                MBARRIER_EXPECT_TX(sb + OFF_MB1, 32768);
                bulk_g2s(sb + OFF_W1,
                         (const char*)g_w1s + ((ch + 1) & 3) * 32768,
                         32768, sb + OFF_MB1);
            }

            // wait W2(ch)
            MBARRIER_WAIT_PARITY(sb + OFF_MB2, p2); p2 ^= 1;

            // ---- GEMM2: out += H(64x128) @ W2c^T, warp tile M32 x N32 ----
            #pragma unroll
            for (int k16 = 0; k16 < 8; k16++) {
                uint32_t a[2][4], b[2][4];
                #pragma unroll
                for (int mi = 0; mi < 2; mi++) {
                    int r = arow0 + mi * 16;
                    ldm_x4(a[mi], sb + OFF_H + r * 256 +
                                  (((2 * k16 + asel) ^ (r & 7)) << 4));
                }
                #pragma unroll
                for (int pr = 0; pr < 2; pr++) {
                    int n = wn * 32 + pr * 16 + brow0;
                    ldm_x4(b[pr], sb + OFF_W2 + n * 256 +
                                  (((2 * k16 + bsel) ^ (n & 7)) << 4));
                }
                #pragma unroll
                for (int mi = 0; mi < 2; mi++)
                    #pragma unroll
                    for (int pr = 0; pr < 2; pr++)
                        #pragma unroll
                        for (int j = 0; j < 2; j++)
                            mma16(out + (mi * 4 + pr * 2 + j) * 4,
                                  a[mi], &b[pr][2 * j]);
            }
            __syncthreads();   // H free for next epilogue; W2 free for reissue
        }  // chunks

        // ---- RK4 stage epilogue (x lives in xout) ----
        #pragma unroll
        for (int mi = 0; mi < 2; mi++)
            #pragma unroll
            for (int ni = 0; ni < 4; ni++) {
                const int q   = (mi * 4 + ni) * 4;
                const int row = wm * 32 + mi * 16 + qr;
                const int col = wn * 32 + ni * 8 + 2 * qc;
                float2* xp0 = (float2*)(xo + row * 128 + col);
                float2* xp1 = (float2*)(xo + (row + 8) * 128 + col);
                float2 xv0 = *xp0, xv1 = *xp1;
                float k0 = out[q + 0] + sB2[col];
                float k1 = out[q + 1] + sB2[col + 1];
                float k2 = out[q + 2] + sB2[col];
                float k3 = out[q + 3] + sB2[col + 1];
                acc[q + 0] += ws * k0; acc[q + 1] += ws * k1;
                acc[q + 2] += ws * k2; acc[q + 3] += ws * k3;
                uint32_t w0, w1;
                if (stage < 3) {
                    w0 = packbf(xv0.x + cs * k0, xv0.y + cs * k1);
                    w1 = packbf(xv1.x + cs * k2, xv1.y + cs * k3);
                } else {
                    float n0 = xv0.x + (DTS / 6.0f) * acc[q + 0];
                    float n1 = xv0.y + (DTS / 6.0f) * acc[q + 1];
                    float n2 = xv1.x + (DTS / 6.0f) * acc[q + 2];
                    float n3 = xv1.y + (DTS / 6.0f) * acc[q + 3];
                    *xp0 = make_float2(n0, n1);
                    *xp1 = make_float2(n2, n3);
                    acc[q + 0] = acc[q + 1] = acc[q + 2] = acc[q + 3] = 0.0f;
                    w0 = packbf(n0, n1);
                    w1 = packbf(n2, n3);
                }
                *(uint32_t*)(smem + OFF_E + row * 256 +
                             ((((col >> 3) ^ (row & 7)) << 4) + (col & 7) * 2)) = w0;
                *(uint32_t*)(smem + OFF_E + (row + 8) * 256 +
                             ((((col >> 3) ^ ((row + 8) & 7)) << 4) +
                              (col & 7) * 2)) = w1;
            }
        __syncthreads();   // E visible before next eval's GEMM1
    }  // evals
}

extern "C" void kernel_launch(void* const* d_in, const int* in_sizes, int n_in,
                              void* d_out, int out_size) {
    const float* x0 = (const float*)d_in[0];
    const float* W1 = (const float*)d_in[1];
    const float* b1 = (const float*)d_in[2];
    const float* W2 = (const float*)d_in[3];
    const float* b2 = (const float*)d_in[4];
    float* out = (float*)d_out;

    static bool configured = false;
    if (!configured) {
        cudaFuncSetAttribute(rk4_kernel,
                             cudaFuncAttributeMaxDynamicSharedMemorySize,
                             SMEM_TOTAL);
        configured = true;
    }

    prep_kernel<<<64, 256>>>(W1, W2);
    rk4_kernel<<<65536 / MROWS, THREADS, SMEM_TOTAL>>>(x0, b1, b2, out);
}